// round 2
// baseline (speedup 1.0000x reference)
#include <cuda_runtime.h>
#include <math.h>

// Problem constants: x (1,64,64,768) -> S=4096 tokens, C=768, 12 heads x 64
#define SS 4096
#define CC 768
#define NH 12
#define HD 64
#define ATT_SCALE 0.125f   // 1/sqrt(64)

// ---------------- scratch (no allocation allowed -> device globals) ----------
__device__ float g_Q[SS * CC];
__device__ float g_K[SS * CC];
__device__ float g_V[SS * CC];
__device__ float g_O[SS * CC];

// ============================================================================
// GEMM (NT): Y[m][n] = sum_k A[m][k] * B[n][k] + bias[n]
// A: [M][K] row-major, B: [N][K] row-major (weights are (out,in)).
// Tile 128x128x16, 256 threads, 8x8 per thread.
// ============================================================================
#define GBM 128
#define GBN 128
#define GBK 16
#define GLDA (GBM + 4)   // 132: pad kills transpose-store bank conflicts,
#define GLDB (GBN + 4)   //      multiple of 4 keeps float4 alignment

__global__ __launch_bounds__(256, 2)
void gemm_nt_bias(const float* __restrict__ A, const float* __restrict__ B,
                  const float* __restrict__ bias, float* __restrict__ Y,
                  int M, int N, int K)
{
    __shared__ float As[GBK][GLDA];
    __shared__ float Bs[GBK][GLDB];

    const int tid = threadIdx.x;
    const int tx = tid & 15;        // 16 cols of threads
    const int ty = tid >> 4;        // 16 rows of threads
    const int m0 = blockIdx.y * GBM;
    const int n0 = blockIdx.x * GBN;

    float acc[8][8];
#pragma unroll
    for (int i = 0; i < 8; i++)
#pragma unroll
        for (int j = 0; j < 8; j++) acc[i][j] = 0.0f;

    // global-load assignment: 128 rows x 16 k per tile; thread -> (row, 8 k)
    const int lr = tid >> 1;          // 0..127
    const int lk = (tid & 1) * 8;     // 0 or 8
    const float* Ag = A + (size_t)(m0 + lr) * K + lk;
    const float* Bg = B + (size_t)(n0 + lr) * K + lk;

    for (int k0 = 0; k0 < K; k0 += GBK) {
        float4 a0 = *(const float4*)(Ag + k0);
        float4 a1 = *(const float4*)(Ag + k0 + 4);
        float4 b0 = *(const float4*)(Bg + k0);
        float4 b1 = *(const float4*)(Bg + k0 + 4);
        __syncthreads();   // previous iteration's readers done
        As[lk + 0][lr] = a0.x; As[lk + 1][lr] = a0.y;
        As[lk + 2][lr] = a0.z; As[lk + 3][lr] = a0.w;
        As[lk + 4][lr] = a1.x; As[lk + 5][lr] = a1.y;
        As[lk + 6][lr] = a1.z; As[lk + 7][lr] = a1.w;
        Bs[lk + 0][lr] = b0.x; Bs[lk + 1][lr] = b0.y;
        Bs[lk + 2][lr] = b0.z; Bs[lk + 3][lr] = b0.w;
        Bs[lk + 4][lr] = b1.x; Bs[lk + 5][lr] = b1.y;
        Bs[lk + 6][lr] = b1.z; Bs[lk + 7][lr] = b1.w;
        __syncthreads();

#pragma unroll
        for (int k = 0; k < GBK; k++) {
            float4 ra0 = *(const float4*)&As[k][ty * 8];
            float4 ra1 = *(const float4*)&As[k][ty * 8 + 4];
            float4 rb0 = *(const float4*)&Bs[k][tx * 8];
            float4 rb1 = *(const float4*)&Bs[k][tx * 8 + 4];
            float ra[8] = { ra0.x, ra0.y, ra0.z, ra0.w, ra1.x, ra1.y, ra1.z, ra1.w };
            float rb[8] = { rb0.x, rb0.y, rb0.z, rb0.w, rb1.x, rb1.y, rb1.z, rb1.w };
#pragma unroll
            for (int i = 0; i < 8; i++)
#pragma unroll
                for (int j = 0; j < 8; j++)
                    acc[i][j] = fmaf(ra[i], rb[j], acc[i][j]);
        }
    }

    // epilogue: + bias, float4 stores
    float4 bb0 = *(const float4*)&bias[n0 + tx * 8];
    float4 bb1 = *(const float4*)&bias[n0 + tx * 8 + 4];
#pragma unroll
    for (int i = 0; i < 8; i++) {
        const int m = m0 + ty * 8 + i;
        float* yr = Y + (size_t)m * N + n0 + tx * 8;
        float4 o0 = make_float4(acc[i][0] + bb0.x, acc[i][1] + bb0.y,
                                acc[i][2] + bb0.z, acc[i][3] + bb0.w);
        float4 o1 = make_float4(acc[i][4] + bb1.x, acc[i][5] + bb1.y,
                                acc[i][6] + bb1.z, acc[i][7] + bb1.w);
        *(float4*)(yr)     = o0;
        *(float4*)(yr + 4) = o1;
    }
}

// ============================================================================
// Flash attention, fp32, online softmax.
// Grid: (S/128 q-blocks, NH heads). Block: 256 threads (16x16).
// q-tile 128 rows x 64 dims; key loop in blocks of 64.
// Q/K/V/O all in merged [S][768] layout; head h = 64-col slice at h*64.
// ============================================================================
#define QB 128
#define KB 64
#define QLD 68
#define KLD 68
#define VLD 68
#define PLD 68
#define ATT_SMEM ((QB*QLD + KB*KLD + KB*VLD + QB*PLD) * 4)   // 104448 bytes

__global__ __launch_bounds__(256)
void attn_kernel(const float* __restrict__ Q, const float* __restrict__ K,
                 const float* __restrict__ V, float* __restrict__ O)
{
    extern __shared__ float sm[];
    float* Qs = sm;                      // [QB][QLD]  (row, dim)
    float* Kt = Qs + QB * QLD;           // [HD][KLD]  (dim, key)   -- transposed
    float* Vs = Kt + KB * KLD;           // [KB][VLD]  (key, dim)
    float* Ps = Vs + KB * VLD;           // [QB][PLD]  (row, key)

    const int tid = threadIdx.x;
    const int tx = tid & 15;             // 16 col-threads: 4 cols each (64 total)
    const int ty = tid >> 4;             // 16 row-threads: 8 rows each (128 total)
    const int h  = blockIdx.y;
    const int q0 = blockIdx.x * QB;
    const int co = h * HD;               // column offset of this head

    // ---- load Q tile once: thread -> (row=tid>>1, 32-dim half) ----
    {
        const int row = tid >> 1;
        const int db  = (tid & 1) * 32;
        const float* g = Q + (size_t)(q0 + row) * CC + co + db;
#pragma unroll
        for (int u = 0; u < 8; u++) {
            float4 v4 = *(const float4*)(g + u * 4);
            *(float4*)&Qs[row * QLD + db + u * 4] = v4;
        }
    }

    float Oa[8][4];
    float mrun[8], lrun[8];
#pragma unroll
    for (int i = 0; i < 8; i++) {
        mrun[i] = -1e30f; lrun[i] = 0.0f;
#pragma unroll
        for (int j = 0; j < 4; j++) Oa[i][j] = 0.0f;
    }

    for (int j0 = 0; j0 < SS; j0 += KB) {
        __syncthreads();   // previous iteration's Kt/Vs/Ps readers done
        // ---- load K (transposed) and V for this key block ----
        {
            const int key = tid >> 2;          // 0..63
            const int db  = (tid & 3) * 16;    // 16-dim quarter
            const float* gk = K + (size_t)(j0 + key) * CC + co + db;
            const float* gv = V + (size_t)(j0 + key) * CC + co + db;
#pragma unroll
            for (int u = 0; u < 4; u++) {
                float4 kv = *(const float4*)(gk + u * 4);
                Kt[(db + u * 4 + 0) * KLD + key] = kv.x;
                Kt[(db + u * 4 + 1) * KLD + key] = kv.y;
                Kt[(db + u * 4 + 2) * KLD + key] = kv.z;
                Kt[(db + u * 4 + 3) * KLD + key] = kv.w;
                float4 vv = *(const float4*)(gv + u * 4);
                *(float4*)&Vs[key * VLD + db + u * 4] = vv;
            }
        }
        __syncthreads();

        // ---- S = Q * K^T  (M=128, N=64, K=64) ----
        float s[8][4];
#pragma unroll
        for (int i = 0; i < 8; i++)
#pragma unroll
            for (int j = 0; j < 4; j++) s[i][j] = 0.0f;

#pragma unroll
        for (int k4 = 0; k4 < HD; k4 += 4) {
            float4 a4[8];
#pragma unroll
            for (int i = 0; i < 8; i++)
                a4[i] = *(const float4*)&Qs[(ty * 8 + i) * QLD + k4];
#pragma unroll
            for (int kk = 0; kk < 4; kk++) {
                float4 b = *(const float4*)&Kt[(k4 + kk) * KLD + tx * 4];
#pragma unroll
                for (int i = 0; i < 8; i++) {
                    const float a = ((const float*)&a4[i])[kk];
                    s[i][0] = fmaf(a, b.x, s[i][0]);
                    s[i][1] = fmaf(a, b.y, s[i][1]);
                    s[i][2] = fmaf(a, b.z, s[i][2]);
                    s[i][3] = fmaf(a, b.w, s[i][3]);
                }
            }
        }

        // ---- online softmax (rows spread over 16 consecutive lanes) ----
#pragma unroll
        for (int i = 0; i < 8; i++) {
#pragma unroll
            for (int j = 0; j < 4; j++) s[i][j] *= ATT_SCALE;
            float m = fmaxf(fmaxf(s[i][0], s[i][1]), fmaxf(s[i][2], s[i][3]));
#pragma unroll
            for (int off = 1; off < 16; off <<= 1)
                m = fmaxf(m, __shfl_xor_sync(0xffffffffu, m, off));
            const float mnew = fmaxf(mrun[i], m);
            const float f = __expf(mrun[i] - mnew);
            float lsum = 0.0f;
#pragma unroll
            for (int j = 0; j < 4; j++) {
                s[i][j] = __expf(s[i][j] - mnew);
                lsum += s[i][j];
            }
#pragma unroll
            for (int off = 1; off < 16; off <<= 1)
                lsum += __shfl_xor_sync(0xffffffffu, lsum, off);
            lrun[i] = lrun[i] * f + lsum;
            mrun[i] = mnew;
#pragma unroll
            for (int j = 0; j < 4; j++) Oa[i][j] *= f;
            *(float4*)&Ps[(ty * 8 + i) * PLD + tx * 4] =
                make_float4(s[i][0], s[i][1], s[i][2], s[i][3]);
        }
        __syncthreads();   // Ps visible to all col-threads

        // ---- O += P * V  (M=128, N=64, K=64 keys) ----
#pragma unroll
        for (int k4 = 0; k4 < KB; k4 += 4) {
            float4 p4[8];
#pragma unroll
            for (int i = 0; i < 8; i++)
                p4[i] = *(const float4*)&Ps[(ty * 8 + i) * PLD + k4];
#pragma unroll
            for (int kk = 0; kk < 4; kk++) {
                float4 v = *(const float4*)&Vs[(k4 + kk) * VLD + tx * 4];
#pragma unroll
                for (int i = 0; i < 8; i++) {
                    const float p = ((const float*)&p4[i])[kk];
                    Oa[i][0] = fmaf(p, v.x, Oa[i][0]);
                    Oa[i][1] = fmaf(p, v.y, Oa[i][1]);
                    Oa[i][2] = fmaf(p, v.z, Oa[i][2]);
                    Oa[i][3] = fmaf(p, v.w, Oa[i][3]);
                }
            }
        }
    }

    // ---- normalize + store (merged layout) ----
#pragma unroll
    for (int i = 0; i < 8; i++) {
        const float inv = 1.0f / lrun[i];
        float* orow = O + (size_t)(q0 + ty * 8 + i) * CC + co + tx * 4;
        *(float4*)orow = make_float4(Oa[i][0] * inv, Oa[i][1] * inv,
                                     Oa[i][2] * inv, Oa[i][3] * inv);
    }
}

// ============================================================================
// launch
// ============================================================================
extern "C" void kernel_launch(void* const* d_in, const int* in_sizes, int n_in,
                              void* d_out, int out_size)
{
    (void)in_sizes; (void)n_in; (void)out_size;
    const float* x  = (const float*)d_in[0];
    const float* Wq = (const float*)d_in[1];
    const float* bq = (const float*)d_in[2];
    const float* Wk = (const float*)d_in[3];
    const float* bk = (const float*)d_in[4];
    const float* Wv = (const float*)d_in[5];
    const float* bv = (const float*)d_in[6];
    const float* Wp = (const float*)d_in[7];
    const float* bp = (const float*)d_in[8];
    float* out = (float*)d_out;

    float *Qp, *Kp, *Vp, *Op;
    cudaGetSymbolAddress((void**)&Qp, g_Q);
    cudaGetSymbolAddress((void**)&Kp, g_K);
    cudaGetSymbolAddress((void**)&Vp, g_V);
    cudaGetSymbolAddress((void**)&Op, g_O);

    // opt-in to >48KB dynamic smem for the attention kernel (idempotent; also
    // executed on the pre-capture correctness call, so the attribute is set
    // before the graph-captured launches regardless).
    cudaFuncSetAttribute(attn_kernel,
                         cudaFuncAttributeMaxDynamicSharedMemorySize, ATT_SMEM);

    const dim3 gproj(CC / GBN, SS / GBM);   // (6, 32)
    gemm_nt_bias<<<gproj, 256>>>(x, Wq, bq, Qp, SS, CC, CC);
    gemm_nt_bias<<<gproj, 256>>>(x, Wk, bk, Kp, SS, CC, CC);
    gemm_nt_bias<<<gproj, 256>>>(x, Wv, bv, Vp, SS, CC, CC);

    const dim3 gattn(SS / QB, NH);          // (32, 12)
    attn_kernel<<<gattn, 256, ATT_SMEM>>>(Qp, Kp, Vp, Op);

    gemm_nt_bias<<<gproj, 256>>>(Op, Wp, bp, out, SS, CC, CC);
}

// round 3
// speedup vs baseline: 2.6193x; 2.6193x over previous
#include <cuda_runtime.h>
#include <cuda_bf16.h>
#include <stdint.h>
#include <math.h>

#define SS 4096
#define CC 768
#define NH 12
#define HD 64

// ---------------- scratch (device globals; no allocation allowed) -----------
__device__ __nv_bfloat16 g_xh[SS * CC], g_xl[SS * CC];
__device__ __nv_bfloat16 g_Wqh[CC * CC], g_Wql[CC * CC];
__device__ __nv_bfloat16 g_Wkh[CC * CC], g_Wkl[CC * CC];
__device__ __nv_bfloat16 g_Wvh[CC * CC], g_Wvl[CC * CC];
__device__ __nv_bfloat16 g_Wph[CC * CC], g_Wpl[CC * CC];
__device__ __nv_bfloat16 g_Qh[SS * CC], g_Ql[SS * CC];
__device__ __nv_bfloat16 g_Kh[SS * CC], g_Kl[SS * CC];
__device__ __nv_bfloat16 g_Vh[SS * CC], g_Vl[SS * CC];
__device__ __nv_bfloat16 g_Oh[SS * CC], g_Ol[SS * CC];

// ---------------- helpers ----------------------------------------------------
__device__ __forceinline__ uint32_t smem_u32(const void* p) {
    uint32_t a;
    asm("{ .reg .u64 t; cvta.to.shared.u64 t, %1; cvt.u32.u64 %0, t; }"
        : "=r"(a) : "l"(p));
    return a;
}

__device__ __forceinline__ void ldsm_x4(uint32_t& r0, uint32_t& r1,
                                        uint32_t& r2, uint32_t& r3, uint32_t addr) {
    asm volatile("ldmatrix.sync.aligned.m8n8.x4.shared.b16 {%0,%1,%2,%3}, [%4];"
        : "=r"(r0), "=r"(r1), "=r"(r2), "=r"(r3) : "r"(addr));
}

__device__ __forceinline__ void ldsm_x4_t(uint32_t& r0, uint32_t& r1,
                                          uint32_t& r2, uint32_t& r3, uint32_t addr) {
    asm volatile("ldmatrix.sync.aligned.m8n8.x4.trans.shared.b16 {%0,%1,%2,%3}, [%4];"
        : "=r"(r0), "=r"(r1), "=r"(r2), "=r"(r3) : "r"(addr));
}

// D += A * B  (m16n8k16, row.col, bf16 in, f32 accum)
__device__ __forceinline__ void mma_bf16(float* d, const uint32_t* a, const uint32_t* b) {
    asm volatile(
        "mma.sync.aligned.m16n8k16.row.col.f32.bf16.bf16.f32 "
        "{%0,%1,%2,%3}, {%4,%5,%6,%7}, {%8,%9}, {%0,%1,%2,%3};"
        : "+f"(d[0]), "+f"(d[1]), "+f"(d[2]), "+f"(d[3])
        : "r"(a[0]), "r"(a[1]), "r"(a[2]), "r"(a[3]), "r"(b[0]), "r"(b[1]));
}

__device__ __forceinline__ uint32_t pack_bf16x2(float v0, float v1) {
    __nv_bfloat162 t = __float22bfloat162_rn(make_float2(v0, v1));  // .x = low = v0
    return *reinterpret_cast<uint32_t*>(&t);
}

// hi/lo split of two fp32 values, packed into two bf16x2 regs
__device__ __forceinline__ void split2(float v0, float v1, uint32_t& hi, uint32_t& lo) {
    __nv_bfloat16 h0 = __float2bfloat16_rn(v0);
    __nv_bfloat16 h1 = __float2bfloat16_rn(v1);
    __nv_bfloat162 hh = __halves2bfloat162(h0, h1);
    hi = *reinterpret_cast<uint32_t*>(&hh);
    lo = pack_bf16x2(v0 - __bfloat162float(h0), v1 - __bfloat162float(h1));
}

// ---------------- fp32 -> (bf16 hi, bf16 lo) conversion ---------------------
__global__ void split_f32(const float* __restrict__ src,
                          __nv_bfloat16* __restrict__ h, __nv_bfloat16* __restrict__ l,
                          int n) {
    int i = blockIdx.x * blockDim.x + threadIdx.x;
    if (i < n) {
        float v = src[i];
        __nv_bfloat16 hb = __float2bfloat16_rn(v);
        h[i] = hb;
        l[i] = __float2bfloat16_rn(v - __bfloat162float(hb));
    }
}

// ============================================================================
// Split-bf16 GEMM (NT):  Y[m][n] = sum_k A[m][k]*B[n][k] + bias[n], x scale
// 3 accumulate passes: Ah*Bh + Al*Bh + Ah*Bl.
// Block 128x128, BK=32, 8 warps (2x4), warp tile 64x32 (4x4 m16n8 frags).
// ============================================================================
#define GP 40   // smem pitch in halves (32 data + 8 pad) -> conflict-free ldmatrix

template <bool SPLIT>
__global__ __launch_bounds__(256, 2)
void gemm_bf16x3(const __nv_bfloat16* __restrict__ Ah, const __nv_bfloat16* __restrict__ Al,
                 const __nv_bfloat16* __restrict__ Bh, const __nv_bfloat16* __restrict__ Bl,
                 const float* __restrict__ bias,
                 float* __restrict__ Yf,
                 __nv_bfloat16* __restrict__ Yh, __nv_bfloat16* __restrict__ Yl,
                 float scale)
{
    __shared__ __align__(16) __nv_bfloat16 As[128 * GP];
    __shared__ __align__(16) __nv_bfloat16 Bs[128 * GP];

    const int tid = threadIdx.x, lane = tid & 31, warp = tid >> 5;
    const int wm = warp >> 2, wn = warp & 3;
    const int m0 = blockIdx.y * 128, n0 = blockIdx.x * 128;

    float acc[4][4][4];
#pragma unroll
    for (int i = 0; i < 4; i++)
#pragma unroll
        for (int j = 0; j < 4; j++)
#pragma unroll
            for (int k = 0; k < 4; k++) acc[i][j][k] = 0.0f;

    const int lr = tid >> 2, lc = tid & 3;     // gmem->smem: row, 16B chunk
    const uint32_t bAs = smem_u32(As), bBs = smem_u32(Bs);
    const int a_row = lane & 15, a_ko = (lane >> 4) << 3;
    const int b_row = (lane & 7) + ((lane >> 4) << 3), b_ko = lane & 8;

    const __nv_bfloat16* APass[3] = { Ah, Al, Ah };
    const __nv_bfloat16* BPass[3] = { Bh, Bh, Bl };

    for (int p = 0; p < 3; p++) {
        const __nv_bfloat16* Ap = APass[p];
        const __nv_bfloat16* Bp = BPass[p];
        for (int k0 = 0; k0 < CC; k0 += 32) {
            uint4 av0 = *(const uint4*)&Ap[(size_t)(m0 + lr) * CC + k0 + lc * 8];
            uint4 av1 = *(const uint4*)&Ap[(size_t)(m0 + lr + 64) * CC + k0 + lc * 8];
            uint4 bv0 = *(const uint4*)&Bp[(size_t)(n0 + lr) * CC + k0 + lc * 8];
            uint4 bv1 = *(const uint4*)&Bp[(size_t)(n0 + lr + 64) * CC + k0 + lc * 8];
            __syncthreads();
            *(uint4*)&As[lr * GP + lc * 8]        = av0;
            *(uint4*)&As[(lr + 64) * GP + lc * 8] = av1;
            *(uint4*)&Bs[lr * GP + lc * 8]        = bv0;
            *(uint4*)&Bs[(lr + 64) * GP + lc * 8] = bv1;
            __syncthreads();

#pragma unroll
            for (int ks = 0; ks < 2; ks++) {
                uint32_t af[4][4], bf_[4][2];
#pragma unroll
                for (int mt = 0; mt < 4; mt++) {
                    uint32_t off = (uint32_t)((wm * 64 + mt * 16 + a_row) * GP
                                              + ks * 16 + a_ko) * 2;
                    ldsm_x4(af[mt][0], af[mt][1], af[mt][2], af[mt][3], bAs + off);
                }
#pragma unroll
                for (int ntp = 0; ntp < 2; ntp++) {
                    uint32_t off = (uint32_t)((wn * 32 + ntp * 16 + b_row) * GP
                                              + ks * 16 + b_ko) * 2;
                    ldsm_x4(bf_[2 * ntp][0], bf_[2 * ntp][1],
                            bf_[2 * ntp + 1][0], bf_[2 * ntp + 1][1], bBs + off);
                }
#pragma unroll
                for (int mt = 0; mt < 4; mt++)
#pragma unroll
                    for (int nt = 0; nt < 4; nt++)
                        mma_bf16(acc[mt][nt], af[mt], bf_[nt]);
            }
        }
    }

    // epilogue
    const int gid = lane >> 2, t2 = lane & 3;
#pragma unroll
    for (int mt = 0; mt < 4; mt++) {
        int r0 = m0 + wm * 64 + mt * 16 + gid;
#pragma unroll
        for (int nt = 0; nt < 4; nt++) {
            int col = n0 + wn * 32 + nt * 8 + t2 * 2;
            float b0 = bias[col], b1 = bias[col + 1];
            float v0 = (acc[mt][nt][0] + b0) * scale;
            float v1 = (acc[mt][nt][1] + b1) * scale;
            float v2 = (acc[mt][nt][2] + b0) * scale;
            float v3 = (acc[mt][nt][3] + b1) * scale;
            if (SPLIT) {
                uint32_t hi, lo;
                split2(v0, v1, hi, lo);
                *(uint32_t*)&Yh[(size_t)r0 * CC + col] = hi;
                *(uint32_t*)&Yl[(size_t)r0 * CC + col] = lo;
                split2(v2, v3, hi, lo);
                *(uint32_t*)&Yh[(size_t)(r0 + 8) * CC + col] = hi;
                *(uint32_t*)&Yl[(size_t)(r0 + 8) * CC + col] = lo;
            } else {
                *(float2*)&Yf[(size_t)r0 * CC + col]       = make_float2(v0, v1);
                *(float2*)&Yf[(size_t)(r0 + 8) * CC + col] = make_float2(v2, v3);
            }
        }
    }
}

// ============================================================================
// Flash attention with split-bf16 mma. Grid (32 q-blocks, 12 heads), 256 thr.
// Each warp owns 16 q-rows; key loop in blocks of 64. Scale folded into Q.
// ============================================================================
#define AP 72   // smem pitch in halves (64 data + 8 pad)
#define ATT_SMEM ((2 * 128 * AP + 4 * 64 * AP) * 2)   // 73728 bytes

__global__ __launch_bounds__(256, 2)
void attn_mma(const __nv_bfloat16* __restrict__ Qh, const __nv_bfloat16* __restrict__ Ql,
              const __nv_bfloat16* __restrict__ Kh, const __nv_bfloat16* __restrict__ Kl,
              const __nv_bfloat16* __restrict__ Vh, const __nv_bfloat16* __restrict__ Vl,
              __nv_bfloat16* __restrict__ Oh, __nv_bfloat16* __restrict__ Ol)
{
    extern __shared__ __align__(16) __nv_bfloat16 sm[];
    __nv_bfloat16* sQh = sm;
    __nv_bfloat16* sQl = sQh + 128 * AP;
    __nv_bfloat16* sKh = sQl + 128 * AP;
    __nv_bfloat16* sKl = sKh + 64 * AP;
    __nv_bfloat16* sVh = sKl + 64 * AP;
    __nv_bfloat16* sVl = sVh + 64 * AP;

    const int tid = threadIdx.x, lane = tid & 31, warp = tid >> 5;
    const int q0 = blockIdx.x * 128;
    const int co = blockIdx.y * HD;

    // ---- load Q tile (hi+lo) ----
#pragma unroll
    for (int i = 0; i < 4; i++) {
        int s = tid + i * 256;
        int row = s >> 3, c = s & 7;
        size_t g = (size_t)(q0 + row) * CC + co + c * 8;
        *(uint4*)&sQh[row * AP + c * 8] = *(const uint4*)&Qh[g];
        *(uint4*)&sQl[row * AP + c * 8] = *(const uint4*)&Ql[g];
    }
    __syncthreads();

    const uint32_t bQh = smem_u32(sQh), bQl = smem_u32(sQl);
    const uint32_t bKh = smem_u32(sKh), bKl = smem_u32(sKl);
    const uint32_t bVh = smem_u32(sVh), bVl = smem_u32(sVl);

    // ---- Q fragments (held in regs for whole kernel) ----
    uint32_t qh[4][4], ql[4][4];
    {
        const int r = warp * 16 + (lane & 15);
        const int kof = (lane >> 4) << 3;
#pragma unroll
        for (int ks = 0; ks < 4; ks++) {
            uint32_t off = (uint32_t)(r * AP + ks * 16 + kof) * 2;
            ldsm_x4(qh[ks][0], qh[ks][1], qh[ks][2], qh[ks][3], bQh + off);
            ldsm_x4(ql[ks][0], ql[ks][1], ql[ks][2], ql[ks][3], bQl + off);
        }
    }

    float m0 = -1e30f, m1 = -1e30f, l0 = 0.0f, l1 = 0.0f;
    float o[8][4];
#pragma unroll
    for (int j = 0; j < 8; j++)
#pragma unroll
        for (int k = 0; k < 4; k++) o[j][k] = 0.0f;

    const int kb_row = (lane & 7) + ((lane >> 4) << 3), kb_ko = lane & 8;
    const int vb_row = (lane & 7) + (lane & 8),         vb_co = (lane >> 4) << 3;

    for (int j0 = 0; j0 < SS; j0 += 64) {
        __syncthreads();
#pragma unroll
        for (int i = 0; i < 2; i++) {
            int s = tid + i * 256;
            int row = s >> 3, c = s & 7;
            size_t g = (size_t)(j0 + row) * CC + co + c * 8;
            uint32_t d = row * AP + c * 8;
            *(uint4*)&sKh[d] = *(const uint4*)&Kh[g];
            *(uint4*)&sKl[d] = *(const uint4*)&Kl[g];
            *(uint4*)&sVh[d] = *(const uint4*)&Vh[g];
            *(uint4*)&sVl[d] = *(const uint4*)&Vl[g];
        }
        __syncthreads();

        // ---- S = Q K^T (3 split terms) ----
        float sf[8][4];
#pragma unroll
        for (int j = 0; j < 8; j++)
#pragma unroll
            for (int k = 0; k < 4; k++) sf[j][k] = 0.0f;

#pragma unroll
        for (int ks = 0; ks < 4; ks++) {
#pragma unroll
            for (int ntp = 0; ntp < 4; ntp++) {
                uint32_t off = (uint32_t)((ntp * 16 + kb_row) * AP
                                          + ks * 16 + kb_ko) * 2;
                uint32_t kh4[4], kl4[4];
                ldsm_x4(kh4[0], kh4[1], kh4[2], kh4[3], bKh + off);
                ldsm_x4(kl4[0], kl4[1], kl4[2], kl4[3], bKl + off);
                mma_bf16(sf[2 * ntp],     qh[ks], &kh4[0]);
                mma_bf16(sf[2 * ntp + 1], qh[ks], &kh4[2]);
                mma_bf16(sf[2 * ntp],     ql[ks], &kh4[0]);
                mma_bf16(sf[2 * ntp + 1], ql[ks], &kh4[2]);
                mma_bf16(sf[2 * ntp],     qh[ks], &kl4[0]);
                mma_bf16(sf[2 * ntp + 1], qh[ks], &kl4[2]);
            }
        }

        // ---- online softmax on fragments (rows r0=gid, r1=gid+8) ----
        float rm0 = -1e30f, rm1 = -1e30f;
#pragma unroll
        for (int j = 0; j < 8; j++) {
            rm0 = fmaxf(rm0, fmaxf(sf[j][0], sf[j][1]));
            rm1 = fmaxf(rm1, fmaxf(sf[j][2], sf[j][3]));
        }
        rm0 = fmaxf(rm0, __shfl_xor_sync(0xffffffffu, rm0, 1));
        rm0 = fmaxf(rm0, __shfl_xor_sync(0xffffffffu, rm0, 2));
        rm1 = fmaxf(rm1, __shfl_xor_sync(0xffffffffu, rm1, 1));
        rm1 = fmaxf(rm1, __shfl_xor_sync(0xffffffffu, rm1, 2));
        float mn0 = fmaxf(m0, rm0), mn1 = fmaxf(m1, rm1);
        float f0 = __expf(m0 - mn0), f1 = __expf(m1 - mn1);
        m0 = mn0; m1 = mn1;
        float s0 = 0.0f, s1 = 0.0f;
#pragma unroll
        for (int j = 0; j < 8; j++) {
            sf[j][0] = __expf(sf[j][0] - mn0);
            sf[j][1] = __expf(sf[j][1] - mn0);
            sf[j][2] = __expf(sf[j][2] - mn1);
            sf[j][3] = __expf(sf[j][3] - mn1);
            s0 += sf[j][0] + sf[j][1];
            s1 += sf[j][2] + sf[j][3];
        }
        s0 += __shfl_xor_sync(0xffffffffu, s0, 1);
        s0 += __shfl_xor_sync(0xffffffffu, s0, 2);
        s1 += __shfl_xor_sync(0xffffffffu, s1, 1);
        s1 += __shfl_xor_sync(0xffffffffu, s1, 2);
        l0 = l0 * f0 + s0;
        l1 = l1 * f1 + s1;
#pragma unroll
        for (int j = 0; j < 8; j++) {
            o[j][0] *= f0; o[j][1] *= f0; o[j][2] *= f1; o[j][3] *= f1;
        }

        // ---- pack P (hi/lo) as A-fragments via D->A repack ----
        uint32_t ph[4][4], pl[4][4];
#pragma unroll
        for (int kk = 0; kk < 4; kk++) {
            split2(sf[2 * kk][0],     sf[2 * kk][1],     ph[kk][0], pl[kk][0]);
            split2(sf[2 * kk][2],     sf[2 * kk][3],     ph[kk][1], pl[kk][1]);
            split2(sf[2 * kk + 1][0], sf[2 * kk + 1][1], ph[kk][2], pl[kk][2]);
            split2(sf[2 * kk + 1][2], sf[2 * kk + 1][3], ph[kk][3], pl[kk][3]);
        }

        // ---- O += P V (3 split terms; V via trans ldmatrix) ----
#pragma unroll
        for (int kk = 0; kk < 4; kk++) {
#pragma unroll
            for (int np = 0; np < 4; np++) {
                uint32_t off = (uint32_t)((kk * 16 + vb_row) * AP
                                          + np * 16 + vb_co) * 2;
                uint32_t vh4[4], vl4[4];
                ldsm_x4_t(vh4[0], vh4[1], vh4[2], vh4[3], bVh + off);
                ldsm_x4_t(vl4[0], vl4[1], vl4[2], vl4[3], bVl + off);
                mma_bf16(o[2 * np],     ph[kk], &vh4[0]);
                mma_bf16(o[2 * np + 1], ph[kk], &vh4[2]);
                mma_bf16(o[2 * np],     pl[kk], &vh4[0]);
                mma_bf16(o[2 * np + 1], pl[kk], &vh4[2]);
                mma_bf16(o[2 * np],     ph[kk], &vl4[0]);
                mma_bf16(o[2 * np + 1], ph[kk], &vl4[2]);
            }
        }
    }

    // ---- normalize + store as bf16 hi/lo ----
    const float i0 = 1.0f / l0, i1 = 1.0f / l1;
    const int gid = lane >> 2, t2 = lane & 3;
    const int r0 = q0 + warp * 16 + gid;
#pragma unroll
    for (int nt = 0; nt < 8; nt++) {
        int col = co + nt * 8 + t2 * 2;
        uint32_t hi, lo;
        split2(o[nt][0] * i0, o[nt][1] * i0, hi, lo);
        *(uint32_t*)&Oh[(size_t)r0 * CC + col] = hi;
        *(uint32_t*)&Ol[(size_t)r0 * CC + col] = lo;
        split2(o[nt][2] * i1, o[nt][3] * i1, hi, lo);
        *(uint32_t*)&Oh[(size_t)(r0 + 8) * CC + col] = hi;
        *(uint32_t*)&Ol[(size_t)(r0 + 8) * CC + col] = lo;
    }
}

// ============================================================================
// launch
// ============================================================================
extern "C" void kernel_launch(void* const* d_in, const int* in_sizes, int n_in,
                              void* d_out, int out_size)
{
    (void)in_sizes; (void)n_in; (void)out_size;
    const float* x  = (const float*)d_in[0];
    const float* Wq = (const float*)d_in[1];
    const float* bq = (const float*)d_in[2];
    const float* Wk = (const float*)d_in[3];
    const float* bk = (const float*)d_in[4];
    const float* Wv = (const float*)d_in[5];
    const float* bv = (const float*)d_in[6];
    const float* Wp = (const float*)d_in[7];
    const float* bp = (const float*)d_in[8];
    float* out = (float*)d_out;

    __nv_bfloat16 *xh, *xl, *Wqh, *Wql, *Wkh, *Wkl, *Wvh, *Wvl, *Wph, *Wpl;
    __nv_bfloat16 *Qh, *Ql, *Kh, *Kl, *Vh, *Vl, *Ohp, *Olp;
    cudaGetSymbolAddress((void**)&xh, g_xh);   cudaGetSymbolAddress((void**)&xl, g_xl);
    cudaGetSymbolAddress((void**)&Wqh, g_Wqh); cudaGetSymbolAddress((void**)&Wql, g_Wql);
    cudaGetSymbolAddress((void**)&Wkh, g_Wkh); cudaGetSymbolAddress((void**)&Wkl, g_Wkl);
    cudaGetSymbolAddress((void**)&Wvh, g_Wvh); cudaGetSymbolAddress((void**)&Wvl, g_Wvl);
    cudaGetSymbolAddress((void**)&Wph, g_Wph); cudaGetSymbolAddress((void**)&Wpl, g_Wpl);
    cudaGetSymbolAddress((void**)&Qh, g_Qh);   cudaGetSymbolAddress((void**)&Ql, g_Ql);
    cudaGetSymbolAddress((void**)&Kh, g_Kh);   cudaGetSymbolAddress((void**)&Kl, g_Kl);
    cudaGetSymbolAddress((void**)&Vh, g_Vh);   cudaGetSymbolAddress((void**)&Vl, g_Vl);
    cudaGetSymbolAddress((void**)&Ohp, g_Oh);  cudaGetSymbolAddress((void**)&Olp, g_Ol);

    cudaFuncSetAttribute(attn_mma,
                         cudaFuncAttributeMaxDynamicSharedMemorySize, ATT_SMEM);

    // input conversions to bf16 hi/lo
    split_f32<<<(SS * CC + 255) / 256, 256>>>(x, xh, xl, SS * CC);
    split_f32<<<(CC * CC + 255) / 256, 256>>>(Wq, Wqh, Wql, CC * CC);
    split_f32<<<(CC * CC + 255) / 256, 256>>>(Wk, Wkh, Wkl, CC * CC);
    split_f32<<<(CC * CC + 255) / 256, 256>>>(Wv, Wvh, Wvl, CC * CC);
    split_f32<<<(CC * CC + 255) / 256, 256>>>(Wp, Wph, Wpl, CC * CC);

    const dim3 gproj(CC / 128, SS / 128);   // (6, 32)
    // Q projection: fold attention scale 0.125 (exact power of two)
    gemm_bf16x3<true><<<gproj, 256>>>(xh, xl, Wqh, Wql, bq, nullptr, Qh, Ql, 0.125f);
    gemm_bf16x3<true><<<gproj, 256>>>(xh, xl, Wkh, Wkl, bk, nullptr, Kh, Kl, 1.0f);
    gemm_bf16x3<true><<<gproj, 256>>>(xh, xl, Wvh, Wvl, bv, nullptr, Vh, Vl, 1.0f);

    const dim3 gattn(SS / 128, NH);         // (32, 12)
    attn_mma<<<gattn, 256, ATT_SMEM>>>(Qh, Ql, Kh, Kl, Vh, Vl, Ohp, Olp);

    gemm_bf16x3<false><<<gproj, 256>>>(Ohp, Olp, Wph, Wpl, bp, out, nullptr, nullptr, 1.0f);
}